// round 15
// baseline (speedup 1.0000x reference)
#include <cuda_runtime.h>
#include <cuda_bf16.h>
#include <cuda_fp16.h>
#include <math_constants.h>
#include <cstdint>

// Problem dims
#define BATCH   256
#define CIN     512
#define KHW     49
#define KD      25088        // 512*49
#define COUT    1000
#define NPAD    1024
#define KSPLIT  16
#define KSEG    (KD / KSPLIT)     // 1568
#define BK      32
#define NCHUNK  (KSEG / BK)       // 49

// top-2 safety margin: fp16 dot abs-error ~3e-4, margin = 60x
#define TOP2_MARGIN 0.02f

// Scratch (device globals only)
__device__ float g_partial[KSPLIT * BATCH * NPAD];   // 16.8 MB
__device__ int   g_top2[BATCH * 2];
__device__ float g_spd_part[BATCH * 4 * 4];          // [n][ct][4]

// ---------------------------------------------------------------------------
// helpers
// ---------------------------------------------------------------------------
__device__ __forceinline__ unsigned packhf(__half a, __half b) {
    unsigned short x = *(unsigned short*)&a;
    unsigned short y = *(unsigned short*)&b;
    return (unsigned)x | ((unsigned)y << 16);
}

__device__ __forceinline__ uint2 packf4(float4 v) {
    return make_uint2(packhf(__float2half_rn(v.x), __float2half_rn(v.y)),
                      packhf(__float2half_rn(v.z), __float2half_rn(v.w)));
}

// fp16 mma, fp32 accumulate
__device__ __forceinline__ void mma16816h(float* d, const unsigned* a, const unsigned* b) {
    asm volatile(
        "mma.sync.aligned.m16n8k16.row.col.f32.f16.f16.f32 "
        "{%0,%1,%2,%3}, {%4,%5,%6,%7}, {%8,%9}, {%0,%1,%2,%3};\n"
        : "+f"(d[0]), "+f"(d[1]), "+f"(d[2]), "+f"(d[3])
        : "r"(a[0]), "r"(a[1]), "r"(a[2]), "r"(a[3]), "r"(b[0]), "r"(b[1]));
}

#define U32S(p) (*reinterpret_cast<const unsigned*>(p))

// ---------------------------------------------------------------------------
// Kernel 1: FC GEMM, fp16 single-pass mma, BK=32 double-buffered smem.
// Prefetch regs hold PACKED fp16 (convert-at-load) -> no spill at 128-reg cap.
// part[ks][m][n] = sum_k A[m,k]*W[n,k]
// grid (8 ntiles, 2 mtiles, 16 ksplit), 256 thr, tile 128x128
// warps 2(m) x 4(n): warp = 64m x 32n
// ---------------------------------------------------------------------------
#define ASTR 40                       // fp16 row stride for BK=32 (+8 pad)
#define GTILE (128 * ASTR * 2)        // 10240 B per matrix
#define GSET  (2 * GTILE)             // A, W per buffer = 20480
#define GEMM_SMEM (2 * GSET)          // 40960

__global__ __launch_bounds__(256, 2) void gemm_mma_kernel(
    const float* __restrict__ A, const float* __restrict__ W)
{
    extern __shared__ char smraw[];

    const int t    = threadIdx.x;
    const int lane = t & 31, wid = t >> 5;
    const int wm = wid >> 2, wn = wid & 3;
    const int g = lane >> 2, tg = lane & 3;

    const int n0 = blockIdx.x * 128;
    const int m0 = blockIdx.y * 128;
    const int k0 = blockIdx.z * KSEG;

    float acc[4][4][4];
#pragma unroll
    for (int a = 0; a < 4; a++)
#pragma unroll
        for (int b = 0; b < 4; b++)
#pragma unroll
            for (int c = 0; c < 4; c++) acc[a][b][c] = 0.f;

    uint2 pa[4], pw[4];   // packed fp16 prefetch (16 regs total)

    auto loadchunk = [&](int c) {
        int kb = k0 + c * BK;
#pragma unroll
        for (int i = 0; i < 4; i++) {
            int idx  = t + i * 256;
            int row  = idx >> 3;
            int kq   = idx & 7;
            float4 va = *(const float4*)(A + (size_t)(m0 + row) * KD + kb + kq * 4);
            pa[i] = packf4(va);
            float4 vw = ((n0 + row) < COUT)
                ? *(const float4*)(W + (size_t)(n0 + row) * KD + kb + kq * 4)
                : make_float4(0.f, 0.f, 0.f, 0.f);
            pw[i] = packf4(vw);
        }
    };
    auto storechunk = [&](int buf) {
        __half* dA = (__half*)(smraw + buf * GSET + 0 * GTILE);
        __half* dW = (__half*)(smraw + buf * GSET + 1 * GTILE);
#pragma unroll
        for (int i = 0; i < 4; i++) {
            int idx  = t + i * 256;
            int row  = idx >> 3;
            int kq   = idx & 7;
            int base = row * ASTR + kq * 4;
            *(uint2*)&dA[base] = pa[i];
            *(uint2*)&dW[base] = pw[i];
        }
    };

    loadchunk(0);
    storechunk(0);
    loadchunk(1);
    __syncthreads();

    for (int c = 0; c < NCHUNK; c++) {
        if (c + 1 < NCHUNK) storechunk((c + 1) & 1);
        if (c + 2 < NCHUNK) loadchunk(c + 2);

        const char* bufp = smraw + (c & 1) * GSET;
        const __half* sA = (const __half*)(bufp + 0 * GTILE);
        const __half* sW = (const __half*)(bufp + 1 * GTILE);

#pragma unroll
        for (int ks = 0; ks < 2; ks++) {
            const int kb = ks * 16;
            unsigned bh[4][2];
#pragma unroll
            for (int ni = 0; ni < 4; ni++) {
                int nr = wn * 32 + ni * 8 + g;
                int base = nr * ASTR + kb + tg * 2;
                bh[ni][0] = U32S(&sW[base]);  bh[ni][1] = U32S(&sW[base + 8]);
            }
#pragma unroll
            for (int mi = 0; mi < 4; mi++) {
                int mr = wm * 64 + mi * 16 + g;
                int base = mr * ASTR + kb + tg * 2;
                unsigned ah[4];
                ah[0] = U32S(&sA[base]);       ah[1] = U32S(&sA[base + 8 * ASTR]);
                ah[2] = U32S(&sA[base + 8]);   ah[3] = U32S(&sA[base + 8 * ASTR + 8]);
#pragma unroll
                for (int ni = 0; ni < 4; ni++)
                    mma16816h(acc[mi][ni], ah, bh[ni]);
            }
        }
        __syncthreads();
    }

    // epilogue: paired STG.64 (v0,v1 and v2,v3 are n-contiguous)
    float* part = g_partial + (size_t)blockIdx.z * BATCH * NPAD;
#pragma unroll
    for (int mi = 0; mi < 4; mi++)
#pragma unroll
        for (int ni = 0; ni < 4; ni++) {
            int n = n0 + wn * 32 + ni * 8 + tg * 2;
            int mA = m0 + wm * 64 + mi * 16 + g;
            *(float2*)&part[(size_t)mA * NPAD + n] =
                make_float2(acc[mi][ni][0], acc[mi][ni][1]);
            *(float2*)&part[(size_t)(mA + 8) * NPAD + n] =
                make_float2(acc[mi][ni][2], acc[mi][ni][3]);
        }
}

// ---------------------------------------------------------------------------
// Kernel 2: fused split-K reduce + bias + top-3, margin-gated exact recheck.
// ---------------------------------------------------------------------------
__global__ __launch_bounds__(256) void reduce_top2_kernel(
    const float* __restrict__ bias, float* __restrict__ outR,
    const float* __restrict__ A, const float* __restrict__ W)
{
    const int m = blockIdx.x;
    const int tid = threadIdx.x;

    // ---- per-thread top-3 ----
    float v[3] = {-CUDART_INF_F, -CUDART_INF_F, -CUDART_INF_F};
    int   id[3] = {0x7fffffff, 0x7fffffff, 0x7fffffff};

    auto ins = [&](float val, int idx) {
        if (val > v[0] || (val == v[0] && idx < id[0])) {
            v[2] = v[1]; id[2] = id[1];
            v[1] = v[0]; id[1] = id[0];
            v[0] = val;  id[0] = idx;
        } else if (val > v[1] || (val == v[1] && idx < id[1])) {
            v[2] = v[1]; id[2] = id[1];
            v[1] = val;  id[1] = idx;
        } else if (val > v[2] || (val == v[2] && idx < id[2])) {
            v[2] = val;  id[2] = idx;
        }
    };

#pragma unroll
    for (int it = 0; it < 4; it++) {
        int n = tid + it * 256;
        if (n >= COUT) break;
        float s = bias[n];
#pragma unroll
        for (int ks = 0; ks < KSPLIT; ks++)
            s += g_partial[(size_t)ks * BATCH * NPAD + (size_t)m * NPAD + n];
        outR[m * COUT + n] = s;
        ins(s, n);
    }

    __shared__ float sv[3 * 256];
    __shared__ int   si[3 * 256];
    __shared__ int   s_skip;
#pragma unroll
    for (int q = 0; q < 3; q++) { sv[q * 256 + tid] = v[q]; si[q * 256 + tid] = id[q]; }
    __syncthreads();

    for (int s = 128; s > 0; s >>= 1) {
        if (tid < s) {
#pragma unroll
            for (int q = 0; q < 3; q++) {
                float ov = sv[q * 256 + tid + s];
                int   oi = si[q * 256 + tid + s];
                ins(ov, oi);
            }
#pragma unroll
            for (int q = 0; q < 3; q++) { sv[q * 256 + tid] = v[q]; si[q * 256 + tid] = id[q]; }
        }
        __syncthreads();
    }

    // candidates (top-3 by approx value) + margin gate
    const int c0 = si[0], c1 = si[256], c2 = si[512];
    if (tid == 0) {
        float g12 = sv[0] - sv[256];
        float g23 = sv[256] - sv[512];
        int skip = (g12 > TOP2_MARGIN) && (g23 > TOP2_MARGIN);
        s_skip = skip;
        if (skip) {
            g_top2[m * 2 + 0] = c0;
            g_top2[m * 2 + 1] = c1;
        }
    }
    __syncthreads();
    if (s_skip) return;

    // ---- exact fp32 recompute of the 3 candidate dot products ----
    const float4* ar = (const float4*)(A + (size_t)m * KD);
    const float4* w0 = (const float4*)(W + (size_t)c0 * KD);
    const float4* w1 = (const float4*)(W + (size_t)c1 * KD);
    const float4* w2 = (const float4*)(W + (size_t)c2 * KD);
    float d0 = 0.f, d1 = 0.f, d2 = 0.f;
    for (int i = tid; i < KD / 4; i += 256) {
        float4 a = ar[i];
        float4 x = w0[i];
        d0 += a.x * x.x + a.y * x.y + a.z * x.z + a.w * x.w;
        float4 y = w1[i];
        d1 += a.x * y.x + a.y * y.y + a.z * y.z + a.w * y.w;
        float4 z = w2[i];
        d2 += a.x * z.x + a.y * z.y + a.z * z.z + a.w * z.w;
    }
    float* red = sv;    // reuse
    red[0 * 256 + tid] = d0;
    red[1 * 256 + tid] = d1;
    red[2 * 256 + tid] = d2;
    __syncthreads();
    for (int s = 128; s > 0; s >>= 1) {
        if (tid < s) {
#pragma unroll
            for (int q = 0; q < 3; q++)
                red[q * 256 + tid] += red[q * 256 + tid + s];
        }
        __syncthreads();
    }

    if (tid == 0) {
        float e[3] = {red[0] + bias[c0], red[256] + bias[c1], red[512] + bias[c2]};
        int   ci[3] = {c0, c1, c2};
#pragma unroll
        for (int q = 0; q < 3; q++) outR[m * COUT + ci[q]] = e[q];
        auto before = [](float va, int ia, float vb, int ib) {
            return va > vb || (va == vb && ia < ib);
        };
        int b0 = 0;
        if (before(e[1], ci[1], e[b0], ci[b0])) b0 = 1;
        if (before(e[2], ci[2], e[b0], ci[b0])) b0 = 2;
        int b1 = -1;
#pragma unroll
        for (int q = 0; q < 3; q++) {
            if (q == b0) continue;
            if (b1 < 0 || before(e[q], ci[q], e[b1], ci[b1])) b1 = q;
        }
        g_top2[m * 2 + 0] = ci[b0];
        g_top2[m * 2 + 1] = ci[b1];
    }
}

// ---------------------------------------------------------------------------
// Kernel 3: SPD path via B = S_n * A_stack, fp16 single-pass mma, N=112.
// Prefetch regs hold PACKED fp16 (convert-at-load): ~110 regs -> 2 CTAs/SM.
// A_stack[d, j]: j in [0,49) -> w0[d*49+j]; j in [49,98) -> w1[d*49+j-49];
// j in [98,112) -> 0.   (j-major smem tile: 112 rows x 64 d-cols)
// grid (4 c-tiles, 256 n), 256 thr, warps 4(c) x 2(j): warp = 32c x 56j.
// ---------------------------------------------------------------------------
#define SSTR 72
#define S_TILE (128 * SSTR * 2)        // 18432 B
#define W_TILEP 16384
#define SBUF   (S_TILE + W_TILEP)      // 34816 per buffer
#define SPD_SMEM (2 * SBUF)            // 69632
#define AFSTR 100

__global__ __launch_bounds__(256, 2) void spd_mma_kernel(
    const float* __restrict__ SPD, const float* __restrict__ W)
{
    extern __shared__ char sm[];

    const int t = threadIdx.x;
    const int lane = t & 31, wid = t >> 5;
    const int wr = wid >> 1, ws = wid & 1;     // 4 c-warps x 2 j-warps
    const int g = lane >> 2, tg = lane & 3;

    const int n  = blockIdx.y;
    const int c0 = blockIdx.x * 128;

    const int o0 = g_top2[n * 2 + 0];
    const int o1 = g_top2[n * 2 + 1];
    const float* w0 = W + (size_t)o0 * KD;
    const float* w1 = W + (size_t)o1 * KD;
    const float* Sn = SPD + (size_t)n * CIN * CIN;

    // zero-pad W rows j in [98,112), d-cols [0,64), both buffers (once)
    for (int idx = t; idx < 2 * 14 * 8; idx += 256) {   // 224 x uint4 (16B)
        int buf = idx / 112;
        int rem = idx - buf * 112;
        int r = rem >> 3, u = rem & 7;
        __half* Wt = (__half*)(sm + buf * SBUF + S_TILE);
        *(uint4*)((char*)&Wt[(98 + r) * SSTR] + u * 16) = make_uint4(0u, 0u, 0u, 0u);
    }

    float acc[2][7][4];
#pragma unroll
    for (int a = 0; a < 2; a++)
#pragma unroll
        for (int b = 0; b < 7; b++)
#pragma unroll
            for (int c = 0; c < 4; c++) acc[a][b][c] = 0.f;

    uint2    psx[8];    // packed fp16 S prefetch (16 regs)
    unsigned pwx[13];   // packed (w0, w1) fp16 pairs (13 regs)

    auto loadchunk = [&](int ch) {
        int dch = ch * 64;
#pragma unroll
        for (int i = 0; i < 8; i++) {
            int idx = t + i * 256;          // 2048 float4 = 128 c-rows x 16
            int c = idx >> 4, q = idx & 15;
            float4 v = *(const float4*)(Sn + (size_t)(c0 + c) * CIN + dch + q * 4);
            psx[i] = packf4(v);
        }
#pragma unroll
        for (int i = 0; i < 13; i++) {
            int idx = t + i * 256;
            if (idx < 3136) {
                float a0 = w0[dch * KHW + idx];
                float a1 = w1[dch * KHW + idx];
                pwx[i] = packhf(__float2half_rn(a0), __float2half_rn(a1));
            }
        }
    };
    auto storechunk = [&](int buf) {
        __half* Sh = (__half*)(sm + buf * SBUF);
        unsigned short* Wt = (unsigned short*)(sm + buf * SBUF + S_TILE);
#pragma unroll
        for (int i = 0; i < 8; i++) {
            int idx = t + i * 256;
            int c = idx >> 4, q = idx & 15;
            *(uint2*)&Sh[c * SSTR + q * 4] = psx[i];
        }
#pragma unroll
        for (int i = 0; i < 13; i++) {
            int idx = t + i * 256;
            if (idx < 3136) {
                int dd = idx / KHW;
                int hw = idx - dd * KHW;
                unsigned p = pwx[i];
                Wt[hw * SSTR + dd]        = (unsigned short)(p & 0xFFFFu);
                Wt[(49 + hw) * SSTR + dd] = (unsigned short)(p >> 16);
            }
        }
    };

    loadchunk(0);
    storechunk(0);
    loadchunk(1);
    __syncthreads();

    for (int ch = 0; ch < 8; ch++) {
        if (ch + 1 < 8) storechunk((ch + 1) & 1);
        if (ch + 2 < 8) loadchunk(ch + 2);

        const __half* Sh = (const __half*)(sm + (ch & 1) * SBUF);
        const __half* Wt = (const __half*)(sm + (ch & 1) * SBUF + S_TILE);

#pragma unroll
        for (int ks = 0; ks < 4; ks++) {
            const int kb = ks * 16;
            unsigned bh[7][2];
#pragma unroll
            for (int ni = 0; ni < 7; ni++) {
                int jr = ws * 56 + ni * 8 + g;
                int base = jr * SSTR + kb + tg * 2;
                bh[ni][0] = U32S(&Wt[base]);  bh[ni][1] = U32S(&Wt[base + 8]);
            }
#pragma unroll
            for (int mi = 0; mi < 2; mi++) {
                int cr = wr * 32 + mi * 16 + g;
                int base = cr * SSTR + kb + tg * 2;
                unsigned ah[4];
                ah[0] = U32S(&Sh[base]);       ah[1] = U32S(&Sh[base + 8 * SSTR]);
                ah[2] = U32S(&Sh[base + 8]);   ah[3] = U32S(&Sh[base + 8 * SSTR + 8]);
#pragma unroll
                for (int ni = 0; ni < 7; ni++)
                    mma16816h(acc[mi][ni], ah, bh[ni]);
            }
        }
        __syncthreads();
    }

    // stage Af[c][hw] = w0 row, Af[c][49+hw] = w1 row (fp32), alias smem
    float* Af = (float*)sm;                 // 128*100*4 = 51200 B
    for (int idx = t; idx < 6272; idx += 256) {
        int c  = idx / KHW;
        int hw = idx - c * KHW;
        Af[c * AFSTR + hw]       = w0[c0 * KHW + idx];
        Af[c * AFSTR + KHW + hw] = w1[c0 * KHW + idx];
    }
    __syncthreads();

    float p00 = 0.f, p01 = 0.f, p10 = 0.f, p11 = 0.f;
#pragma unroll
    for (int mi = 0; mi < 2; mi++)
#pragma unroll
        for (int ni = 0; ni < 7; ni++)
#pragma unroll
            for (int v = 0; v < 4; v++) {
                int c = wr * 32 + mi * 16 + g + ((v >= 2) ? 8 : 0);
                int j = ws * 56 + ni * 8 + tg * 2 + (v & 1);
                float bv = acc[mi][ni][v];
                if (j < KHW) {
                    p00 += Af[c * AFSTR + j] * bv;
                    p01 += Af[c * AFSTR + KHW + j] * bv;
                } else if (j < 2 * KHW) {
                    int hw = j - KHW;
                    p10 += Af[c * AFSTR + hw] * bv;
                    p11 += Af[c * AFSTR + KHW + hw] * bv;
                }
            }

    __syncthreads();
    float* red = (float*)(sm + 52224);      // past Af, 4*256*4 = 4096 B
    red[0 * 256 + t] = p00;
    red[1 * 256 + t] = p01;
    red[2 * 256 + t] = p10;
    red[3 * 256 + t] = p11;
    __syncthreads();
    for (int s = 128; s > 0; s >>= 1) {
        if (t < s) {
#pragma unroll
            for (int q = 0; q < 4; q++)
                red[q * 256 + t] += red[q * 256 + t + s];
        }
        __syncthreads();
    }
    if (t == 0) {
#pragma unroll
        for (int q = 0; q < 4; q++)
            g_spd_part[(n * 4 + blockIdx.x) * 4 + q] = red[q * 256];
    }
}

// ---------------------------------------------------------------------------
// Kernel 4: reduce SPD partials over c-tiles -> outSPD
// ---------------------------------------------------------------------------
__global__ void spd_reduce_kernel(float* __restrict__ outSPD)
{
    int i = blockIdx.x * 256 + threadIdx.x;
    if (i >= BATCH * 4) return;
    int n = i >> 2, q = i & 3;
    float s = 0.f;
#pragma unroll
    for (int dt = 0; dt < 4; dt++)
        s += g_spd_part[(n * 4 + dt) * 4 + q];
    outSPD[i] = s;
}

// ---------------------------------------------------------------------------
extern "C" void kernel_launch(void* const* d_in, const int* in_sizes, int n_in,
                              void* d_out, int out_size)
{
    const float* inputR   = (const float*)d_in[0];   // [256,512,7,7]
    const float* inputSPD = (const float*)d_in[1];   // [256,512,512]
    const float* weight   = (const float*)d_in[2];   // [1000,512,7,7]
    const float* bias     = (const float*)d_in[3];   // [1000]
    float* out = (float*)d_out;

    cudaFuncSetAttribute(gemm_mma_kernel,
                         cudaFuncAttributeMaxDynamicSharedMemorySize, GEMM_SMEM);
    cudaFuncSetAttribute(spd_mma_kernel,
                         cudaFuncAttributeMaxDynamicSharedMemorySize, SPD_SMEM);

    // 1) FC GEMM (fp16 single-pass, BK=32, packed prefetch, 2 CTAs/SM)
    gemm_mma_kernel<<<dim3(8, 2, KSPLIT), 256, GEMM_SMEM>>>(inputR, weight);

    // 2) fused reduce + bias + top-3, margin-gated exact recheck -> top-2
    reduce_top2_kernel<<<BATCH, 256>>>(bias, out, inputR, weight);

    // 3) SPD path: fp16 single-pass mma, N=112, packed prefetch, 2 CTAs/SM
    spd_mma_kernel<<<dim3(4, BATCH), 256, SPD_SMEM>>>(inputSPD, weight);

    // 4) reduce SPD partials
    spd_reduce_kernel<<<4, 256>>>(out + BATCH * COUT);
}

// round 16
// speedup vs baseline: 1.0779x; 1.0779x over previous
#include <cuda_runtime.h>
#include <cuda_bf16.h>
#include <cuda_fp16.h>
#include <math_constants.h>
#include <cstdint>

// Problem dims
#define BATCH   256
#define CIN     512
#define KHW     49
#define KD      25088        // 512*49
#define COUT    1000
#define NPAD    1024
#define KSPLIT  16
#define KSEG    (KD / KSPLIT)     // 1568
#define BK      32
#define NCHUNK  (KSEG / BK)       // 49

// top-2 safety margin: fp16 dot abs-error ~3e-4, margin = 60x
#define TOP2_MARGIN 0.02f

// Scratch (device globals only)
__device__ float g_partial[KSPLIT * BATCH * NPAD];   // 16.8 MB
__device__ int   g_top2[BATCH * 2];
__device__ float g_spd_part[BATCH * 4 * 4];          // [n][ct][4]

// ---------------------------------------------------------------------------
// helpers
// ---------------------------------------------------------------------------
__device__ __forceinline__ unsigned packhf(__half a, __half b) {
    unsigned short x = *(unsigned short*)&a;
    unsigned short y = *(unsigned short*)&b;
    return (unsigned)x | ((unsigned)y << 16);
}

__device__ __forceinline__ unsigned smaddr(const void* p) {
    return (unsigned)__cvta_generic_to_shared(p);
}

__device__ __forceinline__ void ldsm4(unsigned r[4], unsigned a) {
    asm volatile("ldmatrix.sync.aligned.m8n8.x4.shared.b16 {%0,%1,%2,%3}, [%4];"
                 : "=r"(r[0]), "=r"(r[1]), "=r"(r[2]), "=r"(r[3]) : "r"(a));
}

// fp16 mma, fp32 accumulate
__device__ __forceinline__ void mma16816h(float* d, const unsigned* a, const unsigned* b) {
    asm volatile(
        "mma.sync.aligned.m16n8k16.row.col.f32.f16.f16.f32 "
        "{%0,%1,%2,%3}, {%4,%5,%6,%7}, {%8,%9}, {%0,%1,%2,%3};\n"
        : "+f"(d[0]), "+f"(d[1]), "+f"(d[2]), "+f"(d[3])
        : "r"(a[0]), "r"(a[1]), "r"(a[2]), "r"(a[3]), "r"(b[0]), "r"(b[1]));
}

#define U32S(p) (*reinterpret_cast<const unsigned*>(p))

// ---------------------------------------------------------------------------
// Kernel 1: FC GEMM, fp16 single-pass mma, BK=32 double-buffered smem,
// ldmatrix.x4 fragment loads (4x fewer shared-load instructions).
// part[ks][m][n] = sum_k A[m,k]*W[n,k]
// grid (8 ntiles, 2 mtiles, 16 ksplit), 256 thr, tile 128x128
// warps 2(m) x 4(n): warp = 64m x 32n
// ---------------------------------------------------------------------------
#define ASTR 40                       // fp16 row stride for BK=32 (+8 pad)
#define GTILE (128 * ASTR * 2)        // 10240 B per matrix
#define GSET  (2 * GTILE)             // A, W per buffer = 20480
#define GEMM_SMEM (2 * GSET)          // 40960

__global__ __launch_bounds__(256, 2) void gemm_mma_kernel(
    const float* __restrict__ A, const float* __restrict__ W)
{
    extern __shared__ char smraw[];

    const int t    = threadIdx.x;
    const int lane = t & 31, wid = t >> 5;
    const int wm = wid >> 2, wn = wid & 3;
    const int g = lane >> 2, tg = lane & 3;
    const int lr  = lane & 7;
    const int lg1 = (lane >> 3) & 1;
    const int lg2 = lane >> 4;

    const int n0 = blockIdx.x * 128;
    const int m0 = blockIdx.y * 128;
    const int k0 = blockIdx.z * KSEG;

    // loader: 1024 float4 per matrix per chunk, 4 per thread
    int lrow[4], lkq[4];
    bool wvv[4];
#pragma unroll
    for (int i = 0; i < 4; i++) {
        int idx = t + i * 256;
        lrow[i] = idx >> 3;          // 0..127
        lkq[i]  = idx & 7;           // float4 index within 32 k
        wvv[i]  = (n0 + lrow[i]) < COUT;
    }

    float acc[4][4][4];
#pragma unroll
    for (int a = 0; a < 4; a++)
#pragma unroll
        for (int b = 0; b < 4; b++)
#pragma unroll
            for (int c = 0; c < 4; c++) acc[a][b][c] = 0.f;

    float4 pa[4], pw[4];

    auto loadchunk = [&](int c) {
        int kb = k0 + c * BK;
#pragma unroll
        for (int i = 0; i < 4; i++) {
            pa[i] = *(const float4*)(A + (size_t)(m0 + lrow[i]) * KD + kb + lkq[i] * 4);
            pw[i] = wvv[i] ? *(const float4*)(W + (size_t)(n0 + lrow[i]) * KD + kb + lkq[i] * 4)
                           : make_float4(0.f, 0.f, 0.f, 0.f);
        }
    };
    auto storechunk = [&](int buf) {
        __half* dA = (__half*)(smraw + buf * GSET + 0 * GTILE);
        __half* dW = (__half*)(smraw + buf * GSET + 1 * GTILE);
#pragma unroll
        for (int i = 0; i < 4; i++) {
            int base = lrow[i] * ASTR + lkq[i] * 4;
            __half a0 = __float2half_rn(pa[i].x), a1 = __float2half_rn(pa[i].y);
            __half a2 = __float2half_rn(pa[i].z), a3 = __float2half_rn(pa[i].w);
            *(uint2*)&dA[base] = make_uint2(packhf(a0, a1), packhf(a2, a3));
            __half w0 = __float2half_rn(pw[i].x), w1 = __float2half_rn(pw[i].y);
            __half w2 = __float2half_rn(pw[i].z), w3 = __float2half_rn(pw[i].w);
            *(uint2*)&dW[base] = make_uint2(packhf(w0, w1), packhf(w2, w3));
        }
    };

    loadchunk(0);
    storechunk(0);
    loadchunk(1);
    __syncthreads();

    // per-thread LDSM base offsets (bytes)
    const unsigned offA = (unsigned)(((wm * 64 + lr + lg1 * 8) * ASTR + lg2 * 8) * 2);
    const unsigned offB = (unsigned)(((wn * 32 + lr + lg1 * 8) * ASTR + lg2 * 8) * 2);

    for (int c = 0; c < NCHUNK; c++) {
        if (c + 1 < NCHUNK) storechunk((c + 1) & 1);
        if (c + 2 < NCHUNK) loadchunk(c + 2);

        const char* bufp = smraw + (c & 1) * GSET;
        const unsigned aA = smaddr(bufp + 0 * GTILE) + offA;
        const unsigned aW = smaddr(bufp + 1 * GTILE) + offB;

#pragma unroll
        for (int ks = 0; ks < 2; ks++) {
            const unsigned kboff = (unsigned)(ks * 16 * 2);   // 16 halves
            unsigned bh[4][2], r[4];
#pragma unroll
            for (int p = 0; p < 2; p++) {
                ldsm4(r, aW + kboff + p * 16 * ASTR * 2);
                bh[2*p][0] = r[0]; bh[2*p+1][0] = r[1];
                bh[2*p][1] = r[2]; bh[2*p+1][1] = r[3];
            }
#pragma unroll
            for (int mi = 0; mi < 4; mi++) {
                unsigned ah[4];
                ldsm4(ah, aA + kboff + mi * 16 * ASTR * 2);
#pragma unroll
                for (int ni = 0; ni < 4; ni++)
                    mma16816h(acc[mi][ni], ah, bh[ni]);
            }
        }
        __syncthreads();
    }

    // epilogue: paired STG.64 (v0,v1 and v2,v3 are n-contiguous)
    float* part = g_partial + (size_t)blockIdx.z * BATCH * NPAD;
#pragma unroll
    for (int mi = 0; mi < 4; mi++)
#pragma unroll
        for (int ni = 0; ni < 4; ni++) {
            int n = n0 + wn * 32 + ni * 8 + tg * 2;
            int mA = m0 + wm * 64 + mi * 16 + g;
            *(float2*)&part[(size_t)mA * NPAD + n] =
                make_float2(acc[mi][ni][0], acc[mi][ni][1]);
            *(float2*)&part[(size_t)(mA + 8) * NPAD + n] =
                make_float2(acc[mi][ni][2], acc[mi][ni][3]);
        }
}

// ---------------------------------------------------------------------------
// Kernel 2: fused split-K reduce + bias + top-3, margin-gated exact recheck.
// ---------------------------------------------------------------------------
__global__ __launch_bounds__(256) void reduce_top2_kernel(
    const float* __restrict__ bias, float* __restrict__ outR,
    const float* __restrict__ A, const float* __restrict__ W)
{
    const int m = blockIdx.x;
    const int tid = threadIdx.x;

    float v[3] = {-CUDART_INF_F, -CUDART_INF_F, -CUDART_INF_F};
    int   id[3] = {0x7fffffff, 0x7fffffff, 0x7fffffff};

    auto ins = [&](float val, int idx) {
        if (val > v[0] || (val == v[0] && idx < id[0])) {
            v[2] = v[1]; id[2] = id[1];
            v[1] = v[0]; id[1] = id[0];
            v[0] = val;  id[0] = idx;
        } else if (val > v[1] || (val == v[1] && idx < id[1])) {
            v[2] = v[1]; id[2] = id[1];
            v[1] = val;  id[1] = idx;
        } else if (val > v[2] || (val == v[2] && idx < id[2])) {
            v[2] = val;  id[2] = idx;
        }
    };

#pragma unroll
    for (int it = 0; it < 4; it++) {
        int n = tid + it * 256;
        if (n >= COUT) break;
        float s = bias[n];
#pragma unroll
        for (int ks = 0; ks < KSPLIT; ks++)
            s += g_partial[(size_t)ks * BATCH * NPAD + (size_t)m * NPAD + n];
        outR[m * COUT + n] = s;
        ins(s, n);
    }

    __shared__ float sv[3 * 256];
    __shared__ int   si[3 * 256];
    __shared__ int   s_skip;
#pragma unroll
    for (int q = 0; q < 3; q++) { sv[q * 256 + tid] = v[q]; si[q * 256 + tid] = id[q]; }
    __syncthreads();

    for (int s = 128; s > 0; s >>= 1) {
        if (tid < s) {
#pragma unroll
            for (int q = 0; q < 3; q++) {
                float ov = sv[q * 256 + tid + s];
                int   oi = si[q * 256 + tid + s];
                ins(ov, oi);
            }
#pragma unroll
            for (int q = 0; q < 3; q++) { sv[q * 256 + tid] = v[q]; si[q * 256 + tid] = id[q]; }
        }
        __syncthreads();
    }

    const int c0 = si[0], c1 = si[256], c2 = si[512];
    if (tid == 0) {
        float g12 = sv[0] - sv[256];
        float g23 = sv[256] - sv[512];
        int skip = (g12 > TOP2_MARGIN) && (g23 > TOP2_MARGIN);
        s_skip = skip;
        if (skip) {
            g_top2[m * 2 + 0] = c0;
            g_top2[m * 2 + 1] = c1;
        }
    }
    __syncthreads();
    if (s_skip) return;

    // exact fp32 recompute of the 3 candidate dot products
    const float4* ar = (const float4*)(A + (size_t)m * KD);
    const float4* w0 = (const float4*)(W + (size_t)c0 * KD);
    const float4* w1 = (const float4*)(W + (size_t)c1 * KD);
    const float4* w2 = (const float4*)(W + (size_t)c2 * KD);
    float d0 = 0.f, d1 = 0.f, d2 = 0.f;
    for (int i = tid; i < KD / 4; i += 256) {
        float4 a = ar[i];
        float4 x = w0[i];
        d0 += a.x * x.x + a.y * x.y + a.z * x.z + a.w * x.w;
        float4 y = w1[i];
        d1 += a.x * y.x + a.y * y.y + a.z * y.z + a.w * y.w;
        float4 z = w2[i];
        d2 += a.x * z.x + a.y * z.y + a.z * z.z + a.w * z.w;
    }
    float* red = sv;
    red[0 * 256 + tid] = d0;
    red[1 * 256 + tid] = d1;
    red[2 * 256 + tid] = d2;
    __syncthreads();
    for (int s = 128; s > 0; s >>= 1) {
        if (tid < s) {
#pragma unroll
            for (int q = 0; q < 3; q++)
                red[q * 256 + tid] += red[q * 256 + tid + s];
        }
        __syncthreads();
    }

    if (tid == 0) {
        float e[3] = {red[0] + bias[c0], red[256] + bias[c1], red[512] + bias[c2]};
        int   ci[3] = {c0, c1, c2};
#pragma unroll
        for (int q = 0; q < 3; q++) outR[m * COUT + ci[q]] = e[q];
        auto before = [](float va, int ia, float vb, int ib) {
            return va > vb || (va == vb && ia < ib);
        };
        int b0 = 0;
        if (before(e[1], ci[1], e[b0], ci[b0])) b0 = 1;
        if (before(e[2], ci[2], e[b0], ci[b0])) b0 = 2;
        int b1 = -1;
#pragma unroll
        for (int q = 0; q < 3; q++) {
            if (q == b0) continue;
            if (b1 < 0 || before(e[q], ci[q], e[b1], ci[b1])) b1 = q;
        }
        g_top2[m * 2 + 0] = ci[b0];
        g_top2[m * 2 + 1] = ci[b1];
    }
}

// ---------------------------------------------------------------------------
// Kernel 3: SPD path via B = S_n * A_stack, fp16 single-pass mma, N=112.
// (R13 champion version, unchanged.)
// A_stack[d, j]: j in [0,49) -> w0[d*49+j]; j in [49,98) -> w1[d*49+j-49];
// j in [98,112) -> 0.   (j-major smem tile: 112 rows x 64 d-cols)
// grid (4 c-tiles, 256 n), 256 thr, warps 4(c) x 2(j): warp = 32c x 56j.
// ---------------------------------------------------------------------------
#define SSTR 72
#define S_TILE (128 * SSTR * 2)        // 18432 B
#define W_TILEP 16384
#define SBUF   (S_TILE + W_TILEP)      // 34816 per buffer
#define SPD_SMEM (2 * SBUF)            // 69632
#define AFSTR 100

__global__ __launch_bounds__(256) void spd_mma_kernel(
    const float* __restrict__ SPD, const float* __restrict__ W)
{
    extern __shared__ char sm[];

    const int t = threadIdx.x;
    const int lane = t & 31, wid = t >> 5;
    const int wr = wid >> 1, ws = wid & 1;     // 4 c-warps x 2 j-warps
    const int g = lane >> 2, tg = lane & 3;

    const int n  = blockIdx.y;
    const int c0 = blockIdx.x * 128;

    const int o0 = g_top2[n * 2 + 0];
    const int o1 = g_top2[n * 2 + 1];
    const float* w0 = W + (size_t)o0 * KD;
    const float* w1 = W + (size_t)o1 * KD;
    const float* Sn = SPD + (size_t)n * CIN * CIN;

    // zero-pad W rows j in [98,112), d-cols [0,64), both buffers (once)
    for (int idx = t; idx < 2 * 14 * 8; idx += 256) {   // 224 x uint4 (16B)
        int buf = idx / 112;
        int rem = idx - buf * 112;
        int r = rem >> 3, u = rem & 7;
        __half* Wt = (__half*)(sm + buf * SBUF + S_TILE);
        *(uint4*)((char*)&Wt[(98 + r) * SSTR] + u * 16) = make_uint4(0u, 0u, 0u, 0u);
    }

    float acc[2][7][4];
#pragma unroll
    for (int a = 0; a < 2; a++)
#pragma unroll
        for (int b = 0; b < 7; b++)
#pragma unroll
            for (int c = 0; c < 4; c++) acc[a][b][c] = 0.f;

    float4 ps[8];
    float  pw0[13], pw1[13];

    auto loadchunk = [&](int ch) {
        int dch = ch * 64;
#pragma unroll
        for (int i = 0; i < 8; i++) {
            int idx = t + i * 256;          // 2048 float4 = 128 c-rows x 16
            int c = idx >> 4, q = idx & 15;
            ps[i] = *(const float4*)(Sn + (size_t)(c0 + c) * CIN + dch + q * 4);
        }
#pragma unroll
        for (int i = 0; i < 13; i++) {
            int idx = t + i * 256;
            if (idx < 3136) {
                pw0[i] = w0[dch * KHW + idx];
                pw1[i] = w1[dch * KHW + idx];
            }
        }
    };
    auto storechunk = [&](int buf) {
        __half* Sh = (__half*)(sm + buf * SBUF);
        __half* Wt = (__half*)(sm + buf * SBUF + S_TILE);
#pragma unroll
        for (int i = 0; i < 8; i++) {
            int idx = t + i * 256;
            int c = idx >> 4, q = idx & 15;
            int base = c * SSTR + q * 4;
            __half h0 = __float2half_rn(ps[i].x), h1 = __float2half_rn(ps[i].y);
            __half h2 = __float2half_rn(ps[i].z), h3 = __float2half_rn(ps[i].w);
            *(uint2*)&Sh[base] = make_uint2(packhf(h0, h1), packhf(h2, h3));
        }
#pragma unroll
        for (int i = 0; i < 13; i++) {
            int idx = t + i * 256;
            if (idx < 3136) {
                int dd = idx / KHW;
                int hw = idx - dd * KHW;
                Wt[hw * SSTR + dd]        = __float2half_rn(pw0[i]);
                Wt[(49 + hw) * SSTR + dd] = __float2half_rn(pw1[i]);
            }
        }
    };

    loadchunk(0);
    storechunk(0);
    loadchunk(1);
    __syncthreads();

    for (int ch = 0; ch < 8; ch++) {
        if (ch + 1 < 8) storechunk((ch + 1) & 1);
        if (ch + 2 < 8) loadchunk(ch + 2);

        const __half* Sh = (const __half*)(sm + (ch & 1) * SBUF);
        const __half* Wt = (const __half*)(sm + (ch & 1) * SBUF + S_TILE);

#pragma unroll
        for (int ks = 0; ks < 4; ks++) {
            const int kb = ks * 16;
            unsigned bh[7][2];
#pragma unroll
            for (int ni = 0; ni < 7; ni++) {
                int jr = ws * 56 + ni * 8 + g;
                int base = jr * SSTR + kb + tg * 2;
                bh[ni][0] = U32S(&Wt[base]);  bh[ni][1] = U32S(&Wt[base + 8]);
            }
#pragma unroll
            for (int mi = 0; mi < 2; mi++) {
                int cr = wr * 32 + mi * 16 + g;
                int base = cr * SSTR + kb + tg * 2;
                unsigned ah[4];
                ah[0] = U32S(&Sh[base]);       ah[1] = U32S(&Sh[base + 8 * SSTR]);
                ah[2] = U32S(&Sh[base + 8]);   ah[3] = U32S(&Sh[base + 8 * SSTR + 8]);
#pragma unroll
                for (int ni = 0; ni < 7; ni++)
                    mma16816h(acc[mi][ni], ah, bh[ni]);
            }
        }
        __syncthreads();
    }

    // stage Af[c][hw] = w0 row, Af[c][49+hw] = w1 row (fp32), alias smem
    float* Af = (float*)sm;                 // 128*100*4 = 51200 B
    for (int idx = t; idx < 6272; idx += 256) {
        int c  = idx / KHW;
        int hw = idx - c * KHW;
        Af[c * AFSTR + hw]       = w0[c0 * KHW + idx];
        Af[c * AFSTR + KHW + hw] = w1[c0 * KHW + idx];
    }
    __syncthreads();

    float p00 = 0.f, p01 = 0.f, p10 = 0.f, p11 = 0.f;
#pragma unroll
    for (int mi = 0; mi < 2; mi++)
#pragma unroll
        for (int ni = 0; ni < 7; ni++)
#pragma unroll
            for (int v = 0; v < 4; v++) {
                int c = wr * 32 + mi * 16 + g + ((v >= 2) ? 8 : 0);
                int j = ws * 56 + ni * 8 + tg * 2 + (v & 1);
                float bv = acc[mi][ni][v];
                if (j < KHW) {
                    p00 += Af[c * AFSTR + j] * bv;
                    p01 += Af[c * AFSTR + KHW + j] * bv;
                } else if (j < 2 * KHW) {
                    int hw = j - KHW;
                    p10 += Af[c * AFSTR + hw] * bv;
                    p11 += Af[c * AFSTR + KHW + hw] * bv;
                }
            }

    __syncthreads();
    float* red = (float*)(sm + 52224);      // past Af, 4*256*4 = 4096 B
    red[0 * 256 + t] = p00;
    red[1 * 256 + t] = p01;
    red[2 * 256 + t] = p10;
    red[3 * 256 + t] = p11;
    __syncthreads();
    for (int s = 128; s > 0; s >>= 1) {
        if (t < s) {
#pragma unroll
            for (int q = 0; q < 4; q++)
                red[q * 256 + t] += red[q * 256 + t + s];
        }
        __syncthreads();
    }
    if (t == 0) {
#pragma unroll
        for (int q = 0; q < 4; q++)
            g_spd_part[(n * 4 + blockIdx.x) * 4 + q] = red[q * 256];
    }
}

// ---------------------------------------------------------------------------
// Kernel 4: reduce SPD partials over c-tiles -> outSPD
// ---------------------------------------------------------------------------
__global__ void spd_reduce_kernel(float* __restrict__ outSPD)
{
    int i = blockIdx.x * 256 + threadIdx.x;
    if (i >= BATCH * 4) return;
    int n = i >> 2, q = i & 3;
    float s = 0.f;
#pragma unroll
    for (int dt = 0; dt < 4; dt++)
        s += g_spd_part[(n * 4 + dt) * 4 + q];
    outSPD[i] = s;
}

// ---------------------------------------------------------------------------
extern "C" void kernel_launch(void* const* d_in, const int* in_sizes, int n_in,
                              void* d_out, int out_size)
{
    const float* inputR   = (const float*)d_in[0];   // [256,512,7,7]
    const float* inputSPD = (const float*)d_in[1];   // [256,512,512]
    const float* weight   = (const float*)d_in[2];   // [1000,512,7,7]
    const float* bias     = (const float*)d_in[3];   // [1000]
    float* out = (float*)d_out;

    cudaFuncSetAttribute(gemm_mma_kernel,
                         cudaFuncAttributeMaxDynamicSharedMemorySize, GEMM_SMEM);
    cudaFuncSetAttribute(spd_mma_kernel,
                         cudaFuncAttributeMaxDynamicSharedMemorySize, SPD_SMEM);

    // 1) FC GEMM (fp16 single-pass, BK=32, ldmatrix frags, 2 CTAs/SM)
    gemm_mma_kernel<<<dim3(8, 2, KSPLIT), 256, GEMM_SMEM>>>(inputR, weight);

    // 2) fused reduce + bias + top-3, margin-gated exact recheck -> top-2
    reduce_top2_kernel<<<BATCH, 256>>>(bias, out, inputR, weight);

    // 3) SPD path: fp16 single-pass mma, N=112 (R13 champion config)
    spd_mma_kernel<<<dim3(4, BATCH), 256, SPD_SMEM>>>(inputSPD, weight);

    // 4) reduce SPD partials
    spd_reduce_kernel<<<4, 256>>>(out + BATCH * COUT);
}